// round 11
// baseline (speedup 1.0000x reference)
#include <cuda_runtime.h>
#include <cstdint>

#define HH 1024
#define WW 1024
#define TPB   256          // 8 warps per CTA
#define NCTA  16           // 16 CTAs x 8 warps = 128 warps = one per point
#define R0    8            // initial window radius; P(fallback) ~ 1e-12 per point
#define D0    (2 * R0 + 1) // 17
#define CELLS (D0 * D0)    // 289
#define LPL   10           // loads per lane: ceil(289/32)

// Scratch (no allocations allowed)
__device__ float    g_part[NCTA];   // per-CTA partial sums
__device__ unsigned g_cnt;          // finalize ticket (self-resetting)

__device__ __forceinline__ float ld_clamped(const float* __restrict__ m, int r, int c) {
    r = min(max(r, 0), HH - 1);
    c = min(max(c, 0), WW - 1);
    return __ldg(&m[r * WW + c]);
}

__global__ void __launch_bounds__(TPB) road_kernel(const float* __restrict__ map,
                                                   const int*   __restrict__ pred,
                                                   float*       __restrict__ out,
                                                   int N) {
    const int tid  = threadIdx.x;
    const int cta  = blockIdx.x;
    const int lane = tid & 31;
    const int wid  = tid >> 5;

    float wsum = 0.0f;   // this warp's accumulated loss (usually 1 point)

    // Each warp handles points wp = cta*8 + wid, stepping by 128.
    for (int wp = cta * 8 + wid; wp < N; wp += NCTA * 8) {
        const int p0 = __ldg(&pred[2 * wp]);        // converged broadcast load
        const int p1 = __ldg(&pred[2 * wp + 1]);
        // outside_frame uses strict > H / > W (matches reference)
        const bool outside_frame = (p0 < 0) | (p0 > HH) | (p1 < 0) | (p1 > WW);
        if (outside_frame) continue;                // contributes 0

        int best_nd = 0x7FFFFFFF, best_dr = 0x7FFFFFFF;
        float c00, c01, c10, c11;                   // corner values (batched w/ window)

        // ---------- fast path: fixed 17x17 window + 4 corner loads, all batched
        {
            float v[LPL]; int d2[LPL];
#pragma unroll
            for (int u = 0; u < LPL; ++u) {
                unsigned idx = (unsigned)min(lane + u * 32, CELLS - 1); // dup tail cell
                int rr = (int)(idx / (unsigned)D0);
                int cc = (int)(idx - (unsigned)rr * (unsigned)D0);
                int r = min(max(p0 - R0 + rr, 0), HH - 1);   // clamped cell
                int c = min(max(p1 - R0 + cc, 0), WW - 1);   // (dups harmless for min)
                d2[u] = (r - p0) * (r - p0) + (c - p1) * (c - p1);
                v[u]  = __ldg(&map[r * WW + c]);             // independent loads, MLP=10
            }
            // Corner values for outside_road: issued in the SAME batch (no
            // serial round trips later). Broadcast addresses -> 1 wavefront each.
            c00 = ld_clamped(map, p0 - 1, p1 - 1);
            c01 = ld_clamped(map, p0 - 1, p1    );
            c10 = ld_clamped(map, p0,     p1 - 1);
            c11 = ld_clamped(map, p0,     p1    );
#pragma unroll
            for (int u = 0; u < LPL; ++u) {
                if (v[u] != 0.0f) best_nd = min(best_nd, d2[u]);
                else              best_dr = min(best_dr, d2[u]);
            }
        }
        best_nd = __reduce_min_sync(0xFFFFFFFFu, best_nd);
        best_dr = __reduce_min_sync(0xFFFFFFFFu, best_dr);

        // ---------- exactness proof + warp-autonomous doubling fallback ------
        // Window covers every in-bounds cell with Chebyshev dist <= R, so any
        // uncovered cell has d^2 > R^2. If both mins <= R^2 they are exact.
        int R = R0;
        while (!((best_nd <= R * R) && (best_dr <= R * R)) && R < 1024) {
            R <<= 1;
            const int r0 = max(p0 - R, 0), r1 = min(p0 + R, HH - 1);
            const int c0 = max(p1 - R, 0), c1 = min(p1 + R, WW - 1);
            const int nc = c1 - c0 + 1;
            const int total = (r1 - r0 + 1) * nc;
            int bn = 0x7FFFFFFF, bd = 0x7FFFFFFF;
            for (int idx = lane; idx < total; idx += 32) {
                int rr = idx / nc, cc = idx - rr * nc;
                int r = r0 + rr, c = c0 + cc;
                float v = __ldg(&map[r * WW + c]);
                int d2 = (r - p0) * (r - p0) + (c - p1) * (c - p1);
                if (v != 0.0f) bn = min(bn, d2);
                else           bd = min(bd, d2);
            }
            best_nd = __reduce_min_sync(0xFFFFFFFFu, bn);
            best_dr = __reduce_min_sync(0xFFFFFFFFu, bd);
        }

        // ---------- loss on lane 0 (corner bits already in registers) --------
        if (lane == 0) {
            // outside_road: replicate reference's validity masks exactly;
            // non-short-circuit & avoids serialized evaluation.
            const bool rvm1 = (p0 >= 1);
            const bool rv0  = (p0 >= 1) & (p0 < HH);
            const bool cvm1 = (p1 >= 1);
            const bool cv0  = (p1 >= 1) & (p1 < WW);
            const bool outside_road =
                (rvm1 & cvm1 & (c00 != 0.0f)) |
                (rvm1 & cv0  & (c01 != 0.0f)) |
                (rv0  & cvm1 & (c10 != 0.0f)) |
                (rv0  & cv0  & (c11 != 0.0f));
            if (outside_road) {
                // exp(sqrt(min_dr)*ln2/40) - 1 == 2^(sqrt(min_dr)/40) - 1
                wsum += exp2f(sqrtf((float)best_dr) * (1.0f / 40.0f)) - 1.0f;
            } else {
                wsum += expf(-(float)best_nd * (1.0f / 21.7f));
            }
        }
    }

    // ---------- CTA partial: fixed-order sum of 8 warp losses ----------
    __shared__ float wl[8];
    if (lane == 0) wl[wid] = wsum;
    __syncthreads();

    __shared__ bool isLast;
    if (tid == 0) {
        float p = 0.0f;
#pragma unroll
        for (int k = 0; k < 8; ++k) p += wl[k];
        g_part[cta] = p;
        // Release-arrive: orders the g_part store before the ticket increment
        // without a full membar on the critical path.
        unsigned prev;
        asm volatile("atom.release.gpu.global.add.u32 %0, [%1], 1;"
                     : "=r"(prev) : "l"(&g_cnt) : "memory");
        isLast = (prev == (unsigned)(NCTA - 1));
        if (isLast) {
            // Acquire: order subsequent g_part reads after observing all arrivals.
            unsigned dummy;
            asm volatile("atom.acquire.gpu.global.add.u32 %0, [%1], 0;"
                         : "=r"(dummy) : "l"(&g_cnt) : "memory");
        }
    }
    __syncthreads();

    // ---------- last CTA: deterministic fixed-order final sum ----------
    if (isLast && tid == 0) {
        float s = 0.0f;
#pragma unroll
        for (int k = 0; k < NCTA; ++k) {
            float pv;
            asm volatile("ld.global.cg.f32 %0, [%1];" : "=f"(pv) : "l"(&g_part[k]));
            s += pv;
        }
        out[0] = s / (float)N;
        g_cnt = 0u;                             // self-reset for next graph replay
    }
}

extern "C" void kernel_launch(void* const* d_in, const int* in_sizes, int n_in,
                              void* d_out, int out_size) {
    const float* hd_map = (const float*)d_in[0];
    const int*   pred   = (const int*)d_in[1];
    float*       out    = (float*)d_out;
    const int N = in_sizes[1] / 2;   // 128

    road_kernel<<<NCTA, TPB>>>(hd_map, pred, out, N);
}

// round 12
// speedup vs baseline: 1.3112x; 1.3112x over previous
#include <cuda_runtime.h>
#include <cstdint>

#define HH 1024
#define WW 1024
#define TPB   128          // 4 warps per CTA -> one warp per SMSP, no time-slicing
#define NCTA  32           // 32 CTAs x 4 warps = 128 warps = one per point
#define R0    8            // initial window radius; P(fallback) ~ 1e-12 per point
#define D0    (2 * R0 + 1) // 17
#define CELLS (D0 * D0)    // 289
#define LPL   10           // loads per lane: ceil(289/32)

// Packed accumulator: bits[56..63] = CTA arrive count, bits[0..55] = loss sum
// in 2^-32 fixed point. One atomicAdd = arrive + data transport (no fences).
__device__ unsigned long long g_acc;   // reset by last arriver each replay

__device__ __forceinline__ float ld_clamped(const float* __restrict__ m, int r, int c) {
    r = min(max(r, 0), HH - 1);
    c = min(max(c, 0), WW - 1);
    return __ldg(&m[r * WW + c]);
}

__global__ void __launch_bounds__(TPB) road_kernel(const float* __restrict__ map,
                                                   const int2*  __restrict__ pred2,
                                                   float*       __restrict__ out,
                                                   int N) {
    const int tid  = threadIdx.x;
    const int cta  = blockIdx.x;
    const int lane = tid & 31;
    const int wid  = tid >> 5;

    float wsum = 0.0f;   // this warp's accumulated loss (usually 1 point)

    // Each warp handles points wp = cta*4 + wid, stepping by 128.
    for (int wp = cta * 4 + wid; wp < N; wp += NCTA * 4) {
        const int2 p  = __ldg(&pred2[wp]);          // one 64-bit broadcast load
        const int  p0 = p.x, p1 = p.y;
        // outside_frame uses strict > H / > W (matches reference)
        const bool outside_frame = (p0 < 0) | (p0 > HH) | (p1 < 0) | (p1 > WW);
        if (outside_frame) continue;                // contributes 0

        int best_nd = 0x7FFFFFFF, best_dr = 0x7FFFFFFF;
        float c00, c01, c10, c11;                   // corner values (batched w/ window)

        // ---------- fast path: fixed 17x17 window + 4 corner loads, all batched
        {
            float v[LPL]; int d2[LPL];
#pragma unroll
            for (int u = 0; u < LPL; ++u) {
                unsigned idx = (unsigned)min(lane + u * 32, CELLS - 1); // dup tail cell
                int rr = (int)(idx / (unsigned)D0);
                int cc = (int)(idx - (unsigned)rr * (unsigned)D0);
                int r = min(max(p0 - R0 + rr, 0), HH - 1);   // clamped cell
                int c = min(max(p1 - R0 + cc, 0), WW - 1);   // (dups harmless for min)
                d2[u] = (r - p0) * (r - p0) + (c - p1) * (c - p1);
                v[u]  = __ldg(&map[r * WW + c]);             // independent loads, MLP=10
            }
            // Corner values for outside_road: issued in the SAME batch.
            c00 = ld_clamped(map, p0 - 1, p1 - 1);
            c01 = ld_clamped(map, p0 - 1, p1    );
            c10 = ld_clamped(map, p0,     p1 - 1);
            c11 = ld_clamped(map, p0,     p1    );
#pragma unroll
            for (int u = 0; u < LPL; ++u) {
                if (v[u] != 0.0f) best_nd = min(best_nd, d2[u]);
                else              best_dr = min(best_dr, d2[u]);
            }
        }
        best_nd = __reduce_min_sync(0xFFFFFFFFu, best_nd);
        best_dr = __reduce_min_sync(0xFFFFFFFFu, best_dr);

        // ---------- exactness proof + warp-autonomous doubling fallback ------
        // Window covers every in-bounds cell with Chebyshev dist <= R, so any
        // uncovered cell has d^2 > R^2. If both mins <= R^2 they are exact.
        int R = R0;
        while (!((best_nd <= R * R) && (best_dr <= R * R)) && R < 1024) {
            R <<= 1;
            const int r0 = max(p0 - R, 0), r1 = min(p0 + R, HH - 1);
            const int c0 = max(p1 - R, 0), c1 = min(p1 + R, WW - 1);
            const int nc = c1 - c0 + 1;
            const int total = (r1 - r0 + 1) * nc;
            int bn = 0x7FFFFFFF, bd = 0x7FFFFFFF;
            for (int idx = lane; idx < total; idx += 32) {
                int rr = idx / nc, cc = idx - rr * nc;
                int r = r0 + rr, c = c0 + cc;
                float v = __ldg(&map[r * WW + c]);
                int d2 = (r - p0) * (r - p0) + (c - p1) * (c - p1);
                if (v != 0.0f) bn = min(bn, d2);
                else           bd = min(bd, d2);
            }
            best_nd = __reduce_min_sync(0xFFFFFFFFu, bn);
            best_dr = __reduce_min_sync(0xFFFFFFFFu, bd);
        }

        // ---------- loss on lane 0 (corner bits already in registers) --------
        if (lane == 0) {
            // outside_road: replicate reference's validity masks exactly.
            const bool rvm1 = (p0 >= 1);
            const bool rv0  = (p0 >= 1) & (p0 < HH);
            const bool cvm1 = (p1 >= 1);
            const bool cv0  = (p1 >= 1) & (p1 < WW);
            const bool outside_road =
                (rvm1 & cvm1 & (c00 != 0.0f)) |
                (rvm1 & cv0  & (c01 != 0.0f)) |
                (rv0  & cvm1 & (c10 != 0.0f)) |
                (rv0  & cv0  & (c11 != 0.0f));
            if (outside_road) {
                // exp(sqrt(min_dr)*ln2/40) - 1 == 2^(sqrt(min_dr)/40) - 1
                wsum += exp2f(sqrtf((float)best_dr) * (1.0f / 40.0f)) - 1.0f;
            } else {
                wsum += expf(-(float)best_nd * (1.0f / 21.7f));
            }
        }
    }

    // ---------- CTA partial: fixed-order sum of 4 warp losses ----------
    __shared__ float wl[4];
    if (lane == 0) wl[wid] = wsum;
    __syncthreads();

    if (tid == 0) {
        float pcta = wl[0] + wl[1] + wl[2] + wl[3];   // fixed order
        // Clamp protects the packed bit layout; unreachable for valid losses.
        pcta = fminf(pcta, 1048576.0f);
        // 2^-32 fixed point in bits [0..55]; arrive-count 1 in bits [56..63].
        unsigned long long contrib =
            (1ULL << 56) | (unsigned long long)((double)pcta * 4294967296.0);
        unsigned long long prev = atomicAdd(&g_acc, contrib);
        unsigned long long tot  = prev + contrib;
        if ((tot >> 56) == (unsigned long long)NCTA) {      // this CTA was last
            double sum = (double)(tot & ((1ULL << 56) - 1ULL)) * (1.0 / 4294967296.0);
            out[0] = (float)(sum / (double)N);
            g_acc = 0ULL;            // self-reset: everyone has already arrived
        }
    }
}

extern "C" void kernel_launch(void* const* d_in, const int* in_sizes, int n_in,
                              void* d_out, int out_size) {
    const float* hd_map = (const float*)d_in[0];
    const int*   pred   = (const int*)d_in[1];
    float*       out    = (float*)d_out;
    const int N = in_sizes[1] / 2;   // 128

    road_kernel<<<NCTA, TPB>>>(hd_map, (const int2*)pred, out, N);
}